// round 1
// baseline (speedup 1.0000x reference)
#include <cuda_runtime.h>
#include <cuda_bf16.h>
#include <math.h>

#define F 256
#define MAXN 100000
#define MAXE 3200000

// ---------------- device scratch (no allocations allowed) ----------------
__device__ float g_support[(size_t)MAXN * F];   // feature @ W1
__device__ float g_H[(size_t)MAXN * F];         // (A+I) @ support
__device__ float g_Y[(size_t)MAXN * F];         // BNReLU(H) @ W2
__device__ int   g_ptr[MAXN + 1];               // CSR row pointers
__device__ int   g_cursor[MAXN + 1];            // scatter cursors
__device__ int   g_cols[MAXE];                  // CSR col indices (permuted)
__device__ float g_vals[MAXE];                  // CSR values (permuted)
__device__ int   g_bsum[256];                   // scan block sums
__device__ float g_sum[F], g_sumsq[F];          // BN stats accumulators
__device__ float g_a[F], g_b[F];                // BN affine: relu(x*a+b)

// ---------------- CSR construction ----------------
__global__ void k_zero(int n) {
    int i = blockIdx.x * blockDim.x + threadIdx.x;
    if (i < n) g_ptr[i] = 0;
    if (i < F) { g_sum[i] = 0.f; g_sumsq[i] = 0.f; }
}

__global__ void k_hist(const int* __restrict__ rows, int E) {
    int e = blockIdx.x * blockDim.x + threadIdx.x;
    if (e < E) atomicAdd(&g_ptr[rows[e] + 1], 1);
}

// inclusive scan of g_ptr in 1024-element blocks; block totals -> g_bsum
__global__ void k_scan_block(int n) {
    __shared__ int sh[1024];
    int t = threadIdx.x;
    int gid = blockIdx.x * 1024 + t;
    int v = (gid < n) ? g_ptr[gid] : 0;
    sh[t] = v;
    __syncthreads();
    #pragma unroll
    for (int off = 1; off < 1024; off <<= 1) {
        int tv = (t >= off) ? sh[t - off] : 0;
        __syncthreads();
        sh[t] += tv;
        __syncthreads();
    }
    if (gid < n) g_ptr[gid] = sh[t];
    if (t == 1023) g_bsum[blockIdx.x] = sh[1023];
}

// exclusive scan of block sums (nb <= 128)
__global__ void k_scan_sums(int nb) {
    __shared__ int sh[128];
    int t = threadIdx.x;
    int v = (t < nb) ? g_bsum[t] : 0;
    sh[t] = v;
    __syncthreads();
    #pragma unroll
    for (int off = 1; off < 128; off <<= 1) {
        int tv = (t >= off) ? sh[t - off] : 0;
        __syncthreads();
        sh[t] += tv;
        __syncthreads();
    }
    if (t < nb) g_bsum[t] = (t == 0) ? 0 : sh[t - 1];
}

// add block offsets; also initialize scatter cursors
__global__ void k_scan_add(int n) {
    int gid = blockIdx.x * 1024 + threadIdx.x;
    if (gid < n) {
        int v = g_ptr[gid] + g_bsum[blockIdx.x];
        g_ptr[gid] = v;
        g_cursor[gid] = v;
    }
}

__global__ void k_scatter(const int* __restrict__ rows, const int* __restrict__ cols,
                          const float* __restrict__ vals, int E) {
    int e = blockIdx.x * blockDim.x + threadIdx.x;
    if (e < E) {
        int r = rows[e];
        int pos = atomicAdd(&g_cursor[r], 1);
        g_cols[pos] = cols[e];
        g_vals[pos] = vals[e];
    }
}

// ---------------- dense GEMM: C[M,256] = op(A)[M,256] @ W[256,256] ----------------
// op(A) = A, or relu(A*g_a[k]+g_b[k]) per column k when bnrelu != 0.
#define BM 128
#define BN 128
#define BK 16

__global__ void __launch_bounds__(256)
k_gemm(const float* __restrict__ A, const float* __restrict__ W,
       float* __restrict__ C, int M, int bnrelu) {
    __shared__ float As[BK][BM + 4];
    __shared__ float Bs[BK][BN + 4];

    int tid = threadIdx.x;
    int row0 = blockIdx.y * BM;
    int col0 = blockIdx.x * BN;
    int tx = tid & 15;   // 16 col-threads
    int ty = tid >> 4;   // 16 row-threads

    float acc[8][8];
    #pragma unroll
    for (int i = 0; i < 8; i++)
        #pragma unroll
        for (int j = 0; j < 8; j++) acc[i][j] = 0.f;

    for (int k0 = 0; k0 < F; k0 += BK) {
        // load A tile 128x16 (2 float4 per thread)
        #pragma unroll
        for (int i = 0; i < 2; i++) {
            int ar = (tid >> 2) + i * 64;
            int ak = (tid & 3) * 4;
            int grow = row0 + ar;
            float4 v = make_float4(0.f, 0.f, 0.f, 0.f);
            if (grow < M)
                v = *(const float4*)(A + (size_t)grow * F + k0 + ak);
            if (bnrelu) {
                int c = k0 + ak;
                v.x = fmaxf(fmaf(v.x, g_a[c + 0], g_b[c + 0]), 0.f);
                v.y = fmaxf(fmaf(v.y, g_a[c + 1], g_b[c + 1]), 0.f);
                v.z = fmaxf(fmaf(v.z, g_a[c + 2], g_b[c + 2]), 0.f);
                v.w = fmaxf(fmaf(v.w, g_a[c + 3], g_b[c + 3]), 0.f);
            }
            As[ak + 0][ar] = v.x;
            As[ak + 1][ar] = v.y;
            As[ak + 2][ar] = v.z;
            As[ak + 3][ar] = v.w;
        }
        // load W tile 16x128 (2 float4 per thread)
        #pragma unroll
        for (int i = 0; i < 2; i++) {
            int bk = (tid >> 5) + i * 8;
            int bc = (tid & 31) * 4;
            *(float4*)&Bs[bk][bc] = *(const float4*)(W + (size_t)(k0 + bk) * F + col0 + bc);
        }
        __syncthreads();

        #pragma unroll
        for (int k = 0; k < BK; k++) {
            float4 a0 = *(const float4*)&As[k][ty * 8];
            float4 a1 = *(const float4*)&As[k][ty * 8 + 4];
            float4 b0 = *(const float4*)&Bs[k][tx * 8];
            float4 b1 = *(const float4*)&Bs[k][tx * 8 + 4];
            float a[8] = {a0.x, a0.y, a0.z, a0.w, a1.x, a1.y, a1.z, a1.w};
            float b[8] = {b0.x, b0.y, b0.z, b0.w, b1.x, b1.y, b1.z, b1.w};
            #pragma unroll
            for (int i = 0; i < 8; i++)
                #pragma unroll
                for (int j = 0; j < 8; j++)
                    acc[i][j] = fmaf(a[i], b[j], acc[i][j]);
        }
        __syncthreads();
    }

    #pragma unroll
    for (int i = 0; i < 8; i++) {
        int grow = row0 + ty * 8 + i;
        if (grow < M) {
            float4 o0 = make_float4(acc[i][0], acc[i][1], acc[i][2], acc[i][3]);
            float4 o1 = make_float4(acc[i][4], acc[i][5], acc[i][6], acc[i][7]);
            *(float4*)(C + (size_t)grow * F + col0 + tx * 8) = o0;
            *(float4*)(C + (size_t)grow * F + col0 + tx * 8 + 4) = o1;
        }
    }
}

// ---------------- SpMM + self-loop: Y[r] = X[r] + sum_e val*X[col] ----------------
__global__ void __launch_bounds__(256)
k_spmm(const float* __restrict__ X, float* __restrict__ Y, int Nn) {
    int w = (blockIdx.x * 256 + threadIdx.x) >> 5;
    int lane = threadIdx.x & 31;
    if (w >= Nn) return;

    const float4* xs = (const float4*)(X + (size_t)w * F);
    float4 acc0 = xs[lane];        // self loop (+I)
    float4 acc1 = xs[lane + 32];

    int e = g_ptr[w];
    int end = g_ptr[w + 1];
    while (e < end) {
        int m = end - e;
        int c = 0;
        float vv = 0.f;
        if (lane < m) { c = g_cols[e + lane]; vv = g_vals[e + lane]; }
        int cnt = m < 32 ? m : 32;
        for (int j = 0; j < cnt; j++) {
            int cj = __shfl_sync(0xffffffffu, c, j);
            float vj = __shfl_sync(0xffffffffu, vv, j);
            const float4* s = (const float4*)(X + (size_t)cj * F);
            float4 s0 = s[lane];
            float4 s1 = s[lane + 32];
            acc0.x = fmaf(vj, s0.x, acc0.x);
            acc0.y = fmaf(vj, s0.y, acc0.y);
            acc0.z = fmaf(vj, s0.z, acc0.z);
            acc0.w = fmaf(vj, s0.w, acc0.w);
            acc1.x = fmaf(vj, s1.x, acc1.x);
            acc1.y = fmaf(vj, s1.y, acc1.y);
            acc1.z = fmaf(vj, s1.z, acc1.z);
            acc1.w = fmaf(vj, s1.w, acc1.w);
        }
        e += 32;
    }
    float4* o = (float4*)(Y + (size_t)w * F);
    o[lane] = acc0;
    o[lane + 32] = acc1;
}

// ---------------- BN stats ----------------
__global__ void k_stats(const float* __restrict__ H, int M) {
    int c = threadIdx.x;  // 256 threads = 256 columns
    float s = 0.f, s2 = 0.f;
    for (int r = blockIdx.x; r < M; r += gridDim.x) {
        float x = H[(size_t)r * F + c];
        s += x;
        s2 = fmaf(x, x, s2);
    }
    atomicAdd(&g_sum[c], s);
    atomicAdd(&g_sumsq[c], s2);
}

__global__ void k_finalize(int M, const float* __restrict__ gamma,
                           const float* __restrict__ beta) {
    int c = threadIdx.x;
    float invM = 1.f / (float)M;
    float m = g_sum[c] * invM;
    float var = g_sumsq[c] * invM - m * m;
    float r = rsqrtf(var + 1e-5f);
    float a = gamma[c] * r;
    g_a[c] = a;
    g_b[c] = beta[c] - m * a;
}

// ---------------- launch ----------------
extern "C" void kernel_launch(void* const* d_in, const int* in_sizes, int n_in,
                              void* d_out, int out_size) {
    const float* feature = (const float*)d_in[0];
    const int*   rows    = (const int*)d_in[1];
    const int*   cols    = (const int*)d_in[2];
    const float* vals    = (const float*)d_in[3];
    const float* W1      = (const float*)d_in[4];
    const float* W2      = (const float*)d_in[5];
    const float* gamma   = (const float*)d_in[6];
    const float* beta    = (const float*)d_in[7];
    float* out = (float*)d_out;

    int N_ = in_sizes[0] / F;
    int E_ = in_sizes[1];

    float *p_support, *p_H, *p_Y;
    cudaGetSymbolAddress((void**)&p_support, g_support);
    cudaGetSymbolAddress((void**)&p_H, g_H);
    cudaGetSymbolAddress((void**)&p_Y, g_Y);

    int n_ptr = N_ + 1;
    int nb = (n_ptr + 1023) / 1024;

    // CSR build
    k_zero<<<(n_ptr + 255) / 256, 256>>>(n_ptr);
    k_hist<<<(E_ + 255) / 256, 256>>>(rows, E_);
    k_scan_block<<<nb, 1024>>>(n_ptr);
    k_scan_sums<<<1, 128>>>(nb);
    k_scan_add<<<nb, 1024>>>(n_ptr);
    k_scatter<<<(E_ + 255) / 256, 256>>>(rows, cols, vals, E_);

    dim3 ggrid(F / BN, (N_ + BM - 1) / BM);

    // support = feature @ W1
    k_gemm<<<ggrid, 256>>>(feature, W1, p_support, N_, 0);
    // H = (A+I) @ support
    k_spmm<<<(N_ + 7) / 8, 256>>>(p_support, p_H, N_);
    // BN stats over H
    k_stats<<<1024, 256>>>(p_H, N_);
    k_finalize<<<1, 256>>>(N_, gamma, beta);
    // Y = relu(BN(H)) @ W2   (BN fused into A-load)
    k_gemm<<<ggrid, 256>>>(p_H, W2, p_Y, N_, 1);
    // out = (A+I) @ Y
    k_spmm<<<(N_ + 7) / 8, 256>>>(p_Y, out, N_);
}

// round 3
// speedup vs baseline: 1.0932x; 1.0932x over previous
#include <cuda_runtime.h>
#include <cuda_bf16.h>
#include <mma.h>
#include <cstdint>
#include <math.h>

using namespace nvcuda;

#define F 256
#define MAXN 100000
#define MAXE 3200000

// ---------------- device scratch ----------------
__device__ float g_support[(size_t)MAXN * F];
__device__ float g_H[(size_t)MAXN * F];
__device__ float g_Y[(size_t)MAXN * F];
__device__ int   g_ptr[MAXN + 1];
__device__ int   g_cursor[MAXN + 1];
__device__ int   g_cols[MAXE];
__device__ float g_vals[MAXE];
__device__ int   g_bsum[256];
__device__ float g_sum[F], g_sumsq[F];
__device__ float g_a[F], g_b[F];

__device__ __forceinline__ uint32_t smem_u32(const void* p) {
    uint32_t a;
    asm("{ .reg .u64 t; cvta.to.shared.u64 t, %1; cvt.u32.u64 %0, t; }" : "=r"(a) : "l"(p));
    return a;
}

// ---------------- CSR construction ----------------
__global__ void k_zero(int n) {
    int i = blockIdx.x * blockDim.x + threadIdx.x;
    if (i < n) g_ptr[i] = 0;
    if (i < F) { g_sum[i] = 0.f; g_sumsq[i] = 0.f; }
}
__global__ void k_hist(const int* __restrict__ rows, int E) {
    int e = blockIdx.x * blockDim.x + threadIdx.x;
    if (e < E) atomicAdd(&g_ptr[rows[e] + 1], 1);
}
__global__ void k_scan_block(int n) {
    __shared__ int sh[1024];
    int t = threadIdx.x;
    int gid = blockIdx.x * 1024 + t;
    int v = (gid < n) ? g_ptr[gid] : 0;
    sh[t] = v;
    __syncthreads();
    #pragma unroll
    for (int off = 1; off < 1024; off <<= 1) {
        int tv = (t >= off) ? sh[t - off] : 0;
        __syncthreads();
        sh[t] += tv;
        __syncthreads();
    }
    if (gid < n) g_ptr[gid] = sh[t];
    if (t == 1023) g_bsum[blockIdx.x] = sh[1023];
}
__global__ void k_scan_sums(int nb) {
    __shared__ int sh[128];
    int t = threadIdx.x;
    int v = (t < nb) ? g_bsum[t] : 0;
    sh[t] = v;
    __syncthreads();
    #pragma unroll
    for (int off = 1; off < 128; off <<= 1) {
        int tv = (t >= off) ? sh[t - off] : 0;
        __syncthreads();
        sh[t] += tv;
        __syncthreads();
    }
    if (t < nb) g_bsum[t] = (t == 0) ? 0 : sh[t - 1];
}
__global__ void k_scan_add(int n) {
    int gid = blockIdx.x * 1024 + threadIdx.x;
    if (gid < n) {
        int v = g_ptr[gid] + g_bsum[blockIdx.x];
        g_ptr[gid] = v;
        g_cursor[gid] = v;
    }
}
__global__ void k_scatter(const int* __restrict__ rows, const int* __restrict__ cols,
                          const float* __restrict__ vals, int E) {
    int e = blockIdx.x * blockDim.x + threadIdx.x;
    if (e < E) {
        int r = rows[e];
        int pos = atomicAdd(&g_cursor[r], 1);
        g_cols[pos] = cols[e];
        g_vals[pos] = vals[e];
    }
}

// ---------------- tf32 wmma GEMM: C[M,256] = op(A)[M,256] @ W[256,256] ----------------
// op(A) = A, or relu(A*g_a[k]+g_b[k]) when bnrelu != 0 (fused into the A stage).
// CTA: 64 rows x 256 cols, 8 warps (2 row x 4 col), warp tile 32x64.
#define ALD 36
#define BLD 264
#define ASZ (64 * ALD)           // floats
#define BSZ (32 * BLD)
#define STAGE_F (ASZ + BSZ)

__device__ __forceinline__ void cp16(uint32_t dst, const void* src) {
    asm volatile("cp.async.ca.shared.global [%0], [%1], 16;" :: "r"(dst), "l"(src));
}

__global__ void __launch_bounds__(256)
k_gemm_wmma(const float* __restrict__ A, const float* __restrict__ W,
            float* __restrict__ C, int M, int bnrelu) {
    extern __shared__ float sm[];
    int tid = threadIdx.x;
    int wid = tid >> 5;
    int warp_row = wid >> 2;          // 0..1
    int warp_col = wid & 3;           // 0..3
    int row0 = blockIdx.x * 64;

    wmma::fragment<wmma::accumulator, 16, 16, 8, float> acc[2][4];
    #pragma unroll
    for (int i = 0; i < 2; i++)
        #pragma unroll
        for (int j = 0; j < 4; j++) wmma::fill_fragment(acc[i][j], 0.f);

    // per-thread A staging: 2 float4 (64 rows x 32 cols / 256 thr)
    int a_r0 = tid >> 3;              // 0..31  (idx = tid + 0*256)
    int a_c0 = (tid & 7) * 4;
    int a_r1 = a_r0 + 32;             // idx = tid + 256

    float4 areg[2];
    auto load_A = [&](int k0) {
        int gr0 = row0 + a_r0, gr1 = row0 + a_r1;
        areg[0] = (gr0 < M) ? *(const float4*)(A + (size_t)gr0 * F + k0 * 32 + a_c0)
                            : make_float4(0.f, 0.f, 0.f, 0.f);
        areg[1] = (gr1 < M) ? *(const float4*)(A + (size_t)gr1 * F + k0 * 32 + a_c0)
                            : make_float4(0.f, 0.f, 0.f, 0.f);
        if (bnrelu) {
            int c = k0 * 32 + a_c0;
            float a0 = g_a[c], a1 = g_a[c + 1], a2 = g_a[c + 2], a3 = g_a[c + 3];
            float b0 = g_b[c], b1 = g_b[c + 1], b2 = g_b[c + 2], b3 = g_b[c + 3];
            #pragma unroll
            for (int i = 0; i < 2; i++) {
                areg[i].x = fmaxf(fmaf(areg[i].x, a0, b0), 0.f);
                areg[i].y = fmaxf(fmaf(areg[i].y, a1, b1), 0.f);
                areg[i].z = fmaxf(fmaf(areg[i].z, a2, b2), 0.f);
                areg[i].w = fmaxf(fmaf(areg[i].w, a3, b3), 0.f);
            }
        }
    };
    auto sts_A = [&](float* As) {
        *(float4*)(As + a_r0 * ALD + a_c0) = areg[0];
        *(float4*)(As + a_r1 * ALD + a_c0) = areg[1];
    };
    // B: 32 rows x 256 cols via cp.async (8 float4 per thread)
    int b_r = tid >> 3;               // reuse decomposition: idx = tid + i*256 -> r = idx>>6? no:
    auto cpB = [&](float* Bs, int k0) {
        uint32_t bbase = smem_u32(Bs);
        #pragma unroll
        for (int i = 0; i < 8; i++) {
            int idx = tid + i * 256;          // 0..2047 float4 slots
            int r = idx >> 6;                 // 32 rows
            int c4 = (idx & 63) * 4;          // col in floats
            cp16(bbase + (uint32_t)(r * BLD + c4) * 4,
                 W + (size_t)(k0 * 32 + r) * F + c4);
        }
    };

    int buf = 0;
    load_A(0);
    sts_A(sm);
    cpB(sm + ASZ, 0);
    asm volatile("cp.async.commit_group;" ::: "memory");

    for (int k0 = 0; k0 < 8; k0++) {
        if (k0 < 7) load_A(k0 + 1);
        asm volatile("cp.async.wait_group 0;" ::: "memory");
        __syncthreads();
        float* As = sm + buf * STAGE_F;
        float* Bs = As + ASZ;
        if (k0 < 7) {
            float* Asn = sm + (buf ^ 1) * STAGE_F;
            sts_A(Asn);
            cpB(Asn + ASZ, k0 + 1);
            asm volatile("cp.async.commit_group;" ::: "memory");
        }
        #pragma unroll
        for (int kk = 0; kk < 4; kk++) {
            wmma::fragment<wmma::matrix_a, 16, 16, 8, wmma::precision::tf32, wmma::row_major> af[2];
            wmma::fragment<wmma::matrix_b, 16, 16, 8, wmma::precision::tf32, wmma::row_major> bf[4];
            #pragma unroll
            for (int i = 0; i < 2; i++) {
                wmma::load_matrix_sync(af[i], As + (warp_row * 32 + i * 16) * ALD + kk * 8, ALD);
                #pragma unroll
                for (int t = 0; t < af[i].num_elements; t++)
                    af[i].x[t] = wmma::__float_to_tf32(af[i].x[t]);
            }
            #pragma unroll
            for (int j = 0; j < 4; j++) {
                wmma::load_matrix_sync(bf[j], Bs + (kk * 8) * BLD + warp_col * 64 + j * 16, BLD);
                #pragma unroll
                for (int t = 0; t < bf[j].num_elements; t++)
                    bf[j].x[t] = wmma::__float_to_tf32(bf[j].x[t]);
            }
            #pragma unroll
            for (int i = 0; i < 2; i++)
                #pragma unroll
                for (int j = 0; j < 4; j++)
                    wmma::mma_sync(acc[i][j], af[i], bf[j], acc[i][j]);
        }
        __syncthreads();
        buf ^= 1;
    }

    // store: M % 16 == 0, so frag rows are all-in or all-out
    #pragma unroll
    for (int i = 0; i < 2; i++) {
        int rbase = row0 + warp_row * 32 + i * 16;
        if (rbase + 16 <= M) {
            #pragma unroll
            for (int j = 0; j < 4; j++)
                wmma::store_matrix_sync(C + (size_t)rbase * F + warp_col * 64 + j * 16,
                                        acc[i][j], F, wmma::mem_row_major);
        }
    }
}

// ---------------- SpMM + self-loop ----------------
__global__ void __launch_bounds__(256)
k_spmm(const float* __restrict__ X, float* __restrict__ Y, int Nn) {
    int w = (blockIdx.x * 256 + threadIdx.x) >> 5;
    int lane = threadIdx.x & 31;
    if (w >= Nn) return;

    const float4* xs = (const float4*)(X + (size_t)w * F);
    float4 acc0 = xs[lane];
    float4 acc1 = xs[lane + 32];

    int e = g_ptr[w];
    int end = g_ptr[w + 1];
    while (e < end) {
        int m = end - e;
        int c = 0;
        float vv = 0.f;
        if (lane < m) { c = g_cols[e + lane]; vv = g_vals[e + lane]; }
        int cnt = m < 32 ? m : 32;
        for (int j = 0; j < cnt; j++) {
            int cj = __shfl_sync(0xffffffffu, c, j);
            float vj = __shfl_sync(0xffffffffu, vv, j);
            const float4* s = (const float4*)(X + (size_t)cj * F);
            float4 s0 = s[lane];
            float4 s1 = s[lane + 32];
            acc0.x = fmaf(vj, s0.x, acc0.x);
            acc0.y = fmaf(vj, s0.y, acc0.y);
            acc0.z = fmaf(vj, s0.z, acc0.z);
            acc0.w = fmaf(vj, s0.w, acc0.w);
            acc1.x = fmaf(vj, s1.x, acc1.x);
            acc1.y = fmaf(vj, s1.y, acc1.y);
            acc1.z = fmaf(vj, s1.z, acc1.z);
            acc1.w = fmaf(vj, s1.w, acc1.w);
        }
        e += 32;
    }
    float4* o = (float4*)(Y + (size_t)w * F);
    o[lane] = acc0;
    o[lane + 32] = acc1;
}

// ---------------- BN stats ----------------
__global__ void k_stats(const float* __restrict__ H, int M) {
    int c = threadIdx.x;
    float s = 0.f, s2 = 0.f;
    for (int r = blockIdx.x; r < M; r += gridDim.x) {
        float x = H[(size_t)r * F + c];
        s += x;
        s2 = fmaf(x, x, s2);
    }
    atomicAdd(&g_sum[c], s);
    atomicAdd(&g_sumsq[c], s2);
}
__global__ void k_finalize(int M, const float* __restrict__ gamma,
                           const float* __restrict__ beta) {
    int c = threadIdx.x;
    float invM = 1.f / (float)M;
    float m = g_sum[c] * invM;
    float var = g_sumsq[c] * invM - m * m;
    float r = rsqrtf(var + 1e-5f);
    float a = gamma[c] * r;
    g_a[c] = a;
    g_b[c] = beta[c] - m * a;
}

// ---------------- launch ----------------
extern "C" void kernel_launch(void* const* d_in, const int* in_sizes, int n_in,
                              void* d_out, int out_size) {
    const float* feature = (const float*)d_in[0];
    const int*   rows    = (const int*)d_in[1];
    const int*   cols    = (const int*)d_in[2];
    const float* vals    = (const float*)d_in[3];
    const float* W1      = (const float*)d_in[4];
    const float* W2      = (const float*)d_in[5];
    const float* gamma   = (const float*)d_in[6];
    const float* beta    = (const float*)d_in[7];
    float* out = (float*)d_out;

    int N_ = in_sizes[0] / F;
    int E_ = in_sizes[1];

    float *p_support, *p_H, *p_Y;
    cudaGetSymbolAddress((void**)&p_support, g_support);
    cudaGetSymbolAddress((void**)&p_H, g_H);
    cudaGetSymbolAddress((void**)&p_Y, g_Y);

    const int smem_bytes = 2 * STAGE_F * sizeof(float);   // ~86 KB
    cudaFuncSetAttribute(k_gemm_wmma, cudaFuncAttributeMaxDynamicSharedMemorySize, smem_bytes);

    int n_ptr = N_ + 1;
    int nb = (n_ptr + 1023) / 1024;

    // CSR build
    k_zero<<<(n_ptr + 255) / 256, 256>>>(n_ptr);
    k_hist<<<(E_ + 255) / 256, 256>>>(rows, E_);
    k_scan_block<<<nb, 1024>>>(n_ptr);
    k_scan_sums<<<1, 128>>>(nb);
    k_scan_add<<<nb, 1024>>>(n_ptr);
    k_scatter<<<(E_ + 255) / 256, 256>>>(rows, cols, vals, E_);

    int gtiles = (N_ + 63) / 64;

    // support = feature @ W1
    k_gemm_wmma<<<gtiles, 256, smem_bytes>>>(feature, W1, p_support, N_, 0);
    // H = (A+I) @ support
    k_spmm<<<(N_ + 7) / 8, 256>>>(p_support, p_H, N_);
    // BN stats
    k_stats<<<1024, 256>>>(p_H, N_);
    k_finalize<<<1, 256>>>(N_, gamma, beta);
    // Y = relu(BN(H)) @ W2
    k_gemm_wmma<<<gtiles, 256, smem_bytes>>>(p_H, W2, p_Y, N_, 1);
    // out = (A+I) @ Y
    k_spmm<<<(N_ + 7) / 8, 256>>>(p_Y, out, N_);
}

// round 4
// speedup vs baseline: 1.2424x; 1.1365x over previous
#include <cuda_runtime.h>
#include <cuda_bf16.h>
#include <mma.h>
#include <cstdint>
#include <math.h>

using namespace nvcuda;

#define F 256
#define MAXN 100000
#define MAXE 3200000

// ---------------- device scratch ----------------
__device__ float g_support[(size_t)MAXN * F];
__device__ float g_H[(size_t)MAXN * F];
__device__ float g_Y[(size_t)MAXN * F];
__device__ int   g_ptr[MAXN + 1];
__device__ int   g_cursor[MAXN + 1];
__device__ int   g_cols[MAXE];
__device__ float g_vals[MAXE];
__device__ int   g_bsum[256];
__device__ float g_sum[F], g_sumsq[F];
__device__ float g_a[F], g_b[F];
__device__ uint32_t g_Wt[2 * F * F];    // W1, W2 pre-rounded to tf32 bits (row-major)

__device__ __forceinline__ uint32_t smem_u32(const void* p) {
    uint32_t a;
    asm("{ .reg .u64 t; cvta.to.shared.u64 t, %1; cvt.u32.u64 %0, t; }" : "=r"(a) : "l"(p));
    return a;
}
__device__ __forceinline__ float f2tf32f(float x) {
    uint32_t r;
    asm("cvt.rna.tf32.f32 %0, %1;" : "=r"(r) : "f"(x));
    return __uint_as_float(r);
}

// ---------------- CSR construction ----------------
__global__ void k_zero(int n) {
    int i = blockIdx.x * blockDim.x + threadIdx.x;
    if (i < n) g_ptr[i] = 0;
    if (i < F) { g_sum[i] = 0.f; g_sumsq[i] = 0.f; }
}
__global__ void k_hist(const int* __restrict__ rows, int E) {
    int e = blockIdx.x * blockDim.x + threadIdx.x;
    if (e < E) atomicAdd(&g_ptr[rows[e] + 1], 1);
}
__global__ void k_scan_block(int n) {
    __shared__ int sh[1024];
    int t = threadIdx.x;
    int gid = blockIdx.x * 1024 + t;
    int v = (gid < n) ? g_ptr[gid] : 0;
    sh[t] = v;
    __syncthreads();
    #pragma unroll
    for (int off = 1; off < 1024; off <<= 1) {
        int tv = (t >= off) ? sh[t - off] : 0;
        __syncthreads();
        sh[t] += tv;
        __syncthreads();
    }
    if (gid < n) g_ptr[gid] = sh[t];
    if (t == 1023) g_bsum[blockIdx.x] = sh[1023];
}
__global__ void k_scan_sums(int nb) {
    __shared__ int sh[128];
    int t = threadIdx.x;
    int v = (t < nb) ? g_bsum[t] : 0;
    sh[t] = v;
    __syncthreads();
    #pragma unroll
    for (int off = 1; off < 128; off <<= 1) {
        int tv = (t >= off) ? sh[t - off] : 0;
        __syncthreads();
        sh[t] += tv;
        __syncthreads();
    }
    if (t < nb) g_bsum[t] = (t == 0) ? 0 : sh[t - 1];
}
__global__ void k_scan_add(int n) {
    int gid = blockIdx.x * 1024 + threadIdx.x;
    if (gid < n) {
        int v = g_ptr[gid] + g_bsum[blockIdx.x];
        g_ptr[gid] = v;
        g_cursor[gid] = v;
    }
}
__global__ void k_scatter(const int* __restrict__ rows, const int* __restrict__ cols,
                          const float* __restrict__ vals, int E) {
    int e = blockIdx.x * blockDim.x + threadIdx.x;
    if (e < E) {
        int r = rows[e];
        int pos = atomicAdd(&g_cursor[r], 1);
        g_cols[pos] = cols[e];
        g_vals[pos] = vals[e];
    }
}

// ---------------- W pre-round to tf32 (both weights, one kernel) ----------------
__global__ void k_prep_w(const float* __restrict__ W1, const float* __restrict__ W2) {
    int i = blockIdx.x * blockDim.x + threadIdx.x;   // 0 .. 65535
    g_Wt[i]           = __float_as_uint(f2tf32f(W1[i]));
    g_Wt[i + F * F]   = __float_as_uint(f2tf32f(W2[i]));
}

// ---------------- tf32 wmma GEMM: C[M,256] = op(A)[M,256] @ W[256,256] ----------------
#define ALD 36
#define BLD 264
#define ASZ (64 * ALD)
#define BSZ (32 * BLD)
#define STAGE_F (ASZ + BSZ)

__device__ __forceinline__ void cp16(uint32_t dst, const void* src) {
    asm volatile("cp.async.ca.shared.global [%0], [%1], 16;" :: "r"(dst), "l"(src));
}

__global__ void __launch_bounds__(256)
k_gemm_wmma(const float* __restrict__ A, const uint32_t* __restrict__ Wt,
            float* __restrict__ C, int M, int bnrelu) {
    extern __shared__ float sm[];
    int tid = threadIdx.x;
    int wid = tid >> 5;
    int warp_row = wid >> 2;
    int warp_col = wid & 3;
    int row0 = blockIdx.x * 64;

    wmma::fragment<wmma::accumulator, 16, 16, 8, float> acc[2][4];
    #pragma unroll
    for (int i = 0; i < 2; i++)
        #pragma unroll
        for (int j = 0; j < 4; j++) wmma::fill_fragment(acc[i][j], 0.f);

    int a_r0 = tid >> 3;
    int a_c0 = (tid & 7) * 4;
    int a_r1 = a_r0 + 32;

    float4 areg[2];
    auto load_A = [&](int k0) {
        int gr0 = row0 + a_r0, gr1 = row0 + a_r1;
        areg[0] = (gr0 < M) ? *(const float4*)(A + (size_t)gr0 * F + k0 * 32 + a_c0)
                            : make_float4(0.f, 0.f, 0.f, 0.f);
        areg[1] = (gr1 < M) ? *(const float4*)(A + (size_t)gr1 * F + k0 * 32 + a_c0)
                            : make_float4(0.f, 0.f, 0.f, 0.f);
        if (bnrelu) {
            int c = k0 * 32 + a_c0;
            float a0 = g_a[c], a1 = g_a[c + 1], a2 = g_a[c + 2], a3 = g_a[c + 3];
            float b0 = g_b[c], b1 = g_b[c + 1], b2 = g_b[c + 2], b3 = g_b[c + 3];
            #pragma unroll
            for (int i = 0; i < 2; i++) {
                areg[i].x = fmaxf(fmaf(areg[i].x, a0, b0), 0.f);
                areg[i].y = fmaxf(fmaf(areg[i].y, a1, b1), 0.f);
                areg[i].z = fmaxf(fmaf(areg[i].z, a2, b2), 0.f);
                areg[i].w = fmaxf(fmaf(areg[i].w, a3, b3), 0.f);
            }
        }
        // pre-round to tf32 here (once), so no per-fragment conversion later
        #pragma unroll
        for (int i = 0; i < 2; i++) {
            areg[i].x = f2tf32f(areg[i].x);
            areg[i].y = f2tf32f(areg[i].y);
            areg[i].z = f2tf32f(areg[i].z);
            areg[i].w = f2tf32f(areg[i].w);
        }
    };
    auto sts_A = [&](float* As) {
        *(float4*)(As + a_r0 * ALD + a_c0) = areg[0];
        *(float4*)(As + a_r1 * ALD + a_c0) = areg[1];
    };
    auto cpB = [&](float* Bs, int k0) {
        uint32_t bbase = smem_u32(Bs);
        #pragma unroll
        for (int i = 0; i < 8; i++) {
            int idx = tid + i * 256;
            int r = idx >> 6;
            int c4 = (idx & 63) * 4;
            cp16(bbase + (uint32_t)(r * BLD + c4) * 4,
                 Wt + (size_t)(k0 * 32 + r) * F + c4);
        }
    };

    int buf = 0;
    load_A(0);
    sts_A(sm);
    cpB(sm + ASZ, 0);
    asm volatile("cp.async.commit_group;" ::: "memory");

    for (int k0 = 0; k0 < 8; k0++) {
        if (k0 < 7) load_A(k0 + 1);
        asm volatile("cp.async.wait_group 0;" ::: "memory");
        __syncthreads();
        float* As = sm + buf * STAGE_F;
        float* Bs = As + ASZ;
        if (k0 < 7) {
            float* Asn = sm + (buf ^ 1) * STAGE_F;
            sts_A(Asn);
            cpB(Asn + ASZ, k0 + 1);
            asm volatile("cp.async.commit_group;" ::: "memory");
        }
        #pragma unroll
        for (int kk = 0; kk < 4; kk++) {
            wmma::fragment<wmma::matrix_a, 16, 16, 8, wmma::precision::tf32, wmma::row_major> af[2];
            wmma::fragment<wmma::matrix_b, 16, 16, 8, wmma::precision::tf32, wmma::row_major> bf[4];
            #pragma unroll
            for (int i = 0; i < 2; i++)
                wmma::load_matrix_sync(af[i], As + (warp_row * 32 + i * 16) * ALD + kk * 8, ALD);
            #pragma unroll
            for (int j = 0; j < 4; j++)
                wmma::load_matrix_sync(bf[j], Bs + (kk * 8) * BLD + warp_col * 64 + j * 16, BLD);
            #pragma unroll
            for (int i = 0; i < 2; i++)
                #pragma unroll
                for (int j = 0; j < 4; j++)
                    wmma::mma_sync(acc[i][j], af[i], bf[j], acc[i][j]);
        }
        __syncthreads();
        buf ^= 1;
    }

    #pragma unroll
    for (int i = 0; i < 2; i++) {
        int rbase = row0 + warp_row * 32 + i * 16;
        if (rbase + 16 <= M) {
            #pragma unroll
            for (int j = 0; j < 4; j++)
                wmma::store_matrix_sync(C + (size_t)rbase * F + warp_col * 64 + j * 16,
                                        acc[i][j], F, wmma::mem_row_major);
        }
    }
}

// ---------------- SpMM + self-loop: 2 warps per row (128 cols each) ----------------
__global__ void __launch_bounds__(256)
k_spmm(const float* __restrict__ X, float* __restrict__ Y, int Nn) {
    int gw = (blockIdx.x * 256 + threadIdx.x) >> 5;
    int row = gw >> 1;
    int half = gw & 1;
    int lane = threadIdx.x & 31;
    if (row >= Nn) return;

    const float* Xh = X + half * 128;
    float4 acc = *(const float4*)(Xh + (size_t)row * F + lane * 4);   // self loop

    int e = g_ptr[row];
    int end = g_ptr[row + 1];
    while (e < end) {
        int m = end - e;
        int c = 0;
        float vv = 0.f;
        if (lane < m) { c = g_cols[e + lane]; vv = g_vals[e + lane]; }
        int cnt = m < 32 ? m : 32;
        #pragma unroll 4
        for (int j = 0; j < cnt; j++) {
            int cj = __shfl_sync(0xffffffffu, c, j);
            float vj = __shfl_sync(0xffffffffu, vv, j);
            float4 s = *(const float4*)(Xh + (size_t)cj * F + lane * 4);
            acc.x = fmaf(vj, s.x, acc.x);
            acc.y = fmaf(vj, s.y, acc.y);
            acc.z = fmaf(vj, s.z, acc.z);
            acc.w = fmaf(vj, s.w, acc.w);
        }
        e += 32;
    }
    // evict-first store: keep the gather working set (X) resident in L2
    __stcs((float4*)(Y + (size_t)row * F + half * 128 + lane * 4), acc);
}

// ---------------- BN stats ----------------
__global__ void k_stats(const float* __restrict__ H, int M) {
    int c = threadIdx.x;
    float s = 0.f, s2 = 0.f;
    for (int r = blockIdx.x; r < M; r += gridDim.x) {
        float x = __ldcs(H + (size_t)r * F + c);
        s += x;
        s2 = fmaf(x, x, s2);
    }
    atomicAdd(&g_sum[c], s);
    atomicAdd(&g_sumsq[c], s2);
}
__global__ void k_finalize(int M, const float* __restrict__ gamma,
                           const float* __restrict__ beta) {
    int c = threadIdx.x;
    float invM = 1.f / (float)M;
    float m = g_sum[c] * invM;
    float var = g_sumsq[c] * invM - m * m;
    float r = rsqrtf(var + 1e-5f);
    float a = gamma[c] * r;
    g_a[c] = a;
    g_b[c] = beta[c] - m * a;
}

// ---------------- launch ----------------
extern "C" void kernel_launch(void* const* d_in, const int* in_sizes, int n_in,
                              void* d_out, int out_size) {
    const float* feature = (const float*)d_in[0];
    const int*   rows    = (const int*)d_in[1];
    const int*   cols    = (const int*)d_in[2];
    const float* vals    = (const float*)d_in[3];
    const float* W1      = (const float*)d_in[4];
    const float* W2      = (const float*)d_in[5];
    const float* gamma   = (const float*)d_in[6];
    const float* beta    = (const float*)d_in[7];
    float* out = (float*)d_out;

    int N_ = in_sizes[0] / F;
    int E_ = in_sizes[1];

    float *p_support, *p_H, *p_Y;
    uint32_t* p_Wt;
    cudaGetSymbolAddress((void**)&p_support, g_support);
    cudaGetSymbolAddress((void**)&p_H, g_H);
    cudaGetSymbolAddress((void**)&p_Y, g_Y);
    cudaGetSymbolAddress((void**)&p_Wt, g_Wt);

    const int smem_bytes = 2 * STAGE_F * sizeof(float);
    cudaFuncSetAttribute(k_gemm_wmma, cudaFuncAttributeMaxDynamicSharedMemorySize, smem_bytes);

    // lazily created once (first call is the uncaptured correctness run);
    // same handles reused on every call -> identical captured work each time
    static cudaStream_t s2 = nullptr;
    static cudaEvent_t evF = nullptr, evJ = nullptr;
    if (!s2) {
        cudaStreamCreateWithFlags(&s2, cudaStreamNonBlocking);
        cudaEventCreateWithFlags(&evF, cudaEventDisableTiming);
        cudaEventCreateWithFlags(&evJ, cudaEventDisableTiming);
    }

    int n_ptr = N_ + 1;
    int nb = (n_ptr + 1023) / 1024;
    int gtiles = (N_ + 63) / 64;
    int spmm_blocks = (2 * N_ * 32 + 255) / 256;

    // fork: CSR build on s2, concurrent with weight prep + GEMM1 on stream 0
    cudaEventRecord(evF, 0);
    cudaStreamWaitEvent(s2, evF, 0);

    k_zero<<<(n_ptr + 255) / 256, 256, 0, s2>>>(n_ptr);
    k_hist<<<(E_ + 255) / 256, 256, 0, s2>>>(rows, E_);
    k_scan_block<<<nb, 1024, 0, s2>>>(n_ptr);
    k_scan_sums<<<1, 128, 0, s2>>>(nb);
    k_scan_add<<<nb, 1024, 0, s2>>>(n_ptr);
    k_scatter<<<(E_ + 255) / 256, 256, 0, s2>>>(rows, cols, vals, E_);
    cudaEventRecord(evJ, s2);

    k_prep_w<<<F * F / 256, 256>>>(W1, W2);
    k_gemm_wmma<<<gtiles, 256, smem_bytes>>>(feature, p_Wt, p_support, N_, 0);

    // join: SpMM needs CSR
    cudaStreamWaitEvent(0, evJ, 0);

    k_spmm<<<spmm_blocks, 256>>>(p_support, p_H, N_);
    k_stats<<<1024, 256>>>(p_H, N_);
    k_finalize<<<1, 256>>>(N_, gamma, beta);
    k_gemm_wmma<<<gtiles, 256, smem_bytes>>>(p_H, p_Wt + F * F, p_Y, N_, 1);
    k_spmm<<<spmm_blocks, 256>>>(p_Y, out, N_);
}

// round 6
// speedup vs baseline: 1.4449x; 1.1630x over previous
#include <cuda_runtime.h>
#include <cuda_bf16.h>
#include <cuda_fp16.h>
#include <mma.h>
#include <cstdint>
#include <math.h>

using namespace nvcuda;

#define F 256
#define MAXN 100000
#define MAXE 3200000

// ---------------- device scratch ----------------
__device__ float g_support[(size_t)MAXN * F];
__device__ float g_H[(size_t)MAXN * F];
__device__ float g_Y[(size_t)MAXN * F];
__device__ __half g_Xh[(size_t)MAXN * F];       // fp16 copy of the current GEMM output
__device__ int   g_ptr[MAXN + 1];
__device__ int   g_cursor[MAXN + 1];
__device__ int   g_cols[MAXE];
__device__ float g_vals[MAXE];
__device__ int   g_bsum[256];
__device__ float g_sum[F], g_sumsq[F];
__device__ float g_a[F], g_b[F];
__device__ uint32_t g_Wt[2 * F * F];            // W1, W2 pre-rounded to tf32 bits

__device__ __forceinline__ uint32_t smem_u32(const void* p) {
    uint32_t a;
    asm("{ .reg .u64 t; cvta.to.shared.u64 t, %1; cvt.u32.u64 %0, t; }" : "=r"(a) : "l"(p));
    return a;
}
__device__ __forceinline__ float f2tf32f(float x) {
    uint32_t r;
    asm("cvt.rna.tf32.f32 %0, %1;" : "=r"(r) : "f"(x));
    return __uint_as_float(r);
}

// ---------------- CSR construction ----------------
__global__ void k_zero(int n) {
    int i = blockIdx.x * blockDim.x + threadIdx.x;
    if (i < n) g_ptr[i] = 0;
    if (i < F) { g_sum[i] = 0.f; g_sumsq[i] = 0.f; }
}
__global__ void k_hist(const int* __restrict__ rows, int E) {
    int e = blockIdx.x * blockDim.x + threadIdx.x;
    if (e < E) atomicAdd(&g_ptr[rows[e] + 1], 1);
}
__global__ void k_scan_block(int n) {
    __shared__ int sh[1024];
    int t = threadIdx.x;
    int gid = blockIdx.x * 1024 + t;
    int v = (gid < n) ? g_ptr[gid] : 0;
    sh[t] = v;
    __syncthreads();
    #pragma unroll
    for (int off = 1; off < 1024; off <<= 1) {
        int tv = (t >= off) ? sh[t - off] : 0;
        __syncthreads();
        sh[t] += tv;
        __syncthreads();
    }
    if (gid < n) g_ptr[gid] = sh[t];
    if (t == 1023) g_bsum[blockIdx.x] = sh[1023];
}
__global__ void k_scan_sums(int nb) {
    __shared__ int sh[128];
    int t = threadIdx.x;
    int v = (t < nb) ? g_bsum[t] : 0;
    sh[t] = v;
    __syncthreads();
    #pragma unroll
    for (int off = 1; off < 128; off <<= 1) {
        int tv = (t >= off) ? sh[t - off] : 0;
        __syncthreads();
        sh[t] += tv;
        __syncthreads();
    }
    if (t < nb) g_bsum[t] = (t == 0) ? 0 : sh[t - 1];
}
__global__ void k_scan_add(int n) {
    int gid = blockIdx.x * 1024 + threadIdx.x;
    if (gid < n) {
        int v = g_ptr[gid] + g_bsum[blockIdx.x];
        g_ptr[gid] = v;
        g_cursor[gid] = v;
    }
}
__global__ void k_scatter(const int* __restrict__ rows, const int* __restrict__ cols,
                          const float* __restrict__ vals, int E) {
    int e = blockIdx.x * blockDim.x + threadIdx.x;
    if (e < E) {
        int r = rows[e];
        int pos = atomicAdd(&g_cursor[r], 1);
        g_cols[pos] = cols[e];
        g_vals[pos] = vals[e];
    }
}

// ---------------- W pre-round to tf32 ----------------
__global__ void k_prep_w(const float* __restrict__ W1, const float* __restrict__ W2) {
    int i = blockIdx.x * blockDim.x + threadIdx.x;
    g_Wt[i]         = __float_as_uint(f2tf32f(W1[i]));
    g_Wt[i + F * F] = __float_as_uint(f2tf32f(W2[i]));
}

// ---------------- tf32 wmma GEMM + dual-precision output ----------------
#define ALD 36
#define BLD 264
#define ASZ (64 * ALD)
#define BSZ (32 * BLD)
#define STAGE_F (ASZ + BSZ)
#define EPLD 264

__device__ __forceinline__ void cp16(uint32_t dst, const void* src) {
    asm volatile("cp.async.ca.shared.global [%0], [%1], 16;" :: "r"(dst), "l"(src));
}

__global__ void __launch_bounds__(256)
k_gemm_wmma(const float* __restrict__ A, const uint32_t* __restrict__ Wt,
            float* __restrict__ C, __half* __restrict__ Ch, int M, int bnrelu) {
    extern __shared__ float sm[];
    int tid = threadIdx.x;
    int wid = tid >> 5;
    int warp_row = wid >> 2;
    int warp_col = wid & 3;
    int row0 = blockIdx.x * 64;

    wmma::fragment<wmma::accumulator, 16, 16, 8, float> acc[2][4];
    #pragma unroll
    for (int i = 0; i < 2; i++)
        #pragma unroll
        for (int j = 0; j < 4; j++) wmma::fill_fragment(acc[i][j], 0.f);

    int a_r0 = tid >> 3;
    int a_c0 = (tid & 7) * 4;
    int a_r1 = a_r0 + 32;

    float4 areg[2];
    auto load_A = [&](int k0) {
        int gr0 = row0 + a_r0, gr1 = row0 + a_r1;
        areg[0] = (gr0 < M) ? *(const float4*)(A + (size_t)gr0 * F + k0 * 32 + a_c0)
                            : make_float4(0.f, 0.f, 0.f, 0.f);
        areg[1] = (gr1 < M) ? *(const float4*)(A + (size_t)gr1 * F + k0 * 32 + a_c0)
                            : make_float4(0.f, 0.f, 0.f, 0.f);
        if (bnrelu) {
            int c = k0 * 32 + a_c0;
            float a0 = g_a[c], a1 = g_a[c + 1], a2 = g_a[c + 2], a3 = g_a[c + 3];
            float b0 = g_b[c], b1 = g_b[c + 1], b2 = g_b[c + 2], b3 = g_b[c + 3];
            #pragma unroll
            for (int i = 0; i < 2; i++) {
                areg[i].x = fmaxf(fmaf(areg[i].x, a0, b0), 0.f);
                areg[i].y = fmaxf(fmaf(areg[i].y, a1, b1), 0.f);
                areg[i].z = fmaxf(fmaf(areg[i].z, a2, b2), 0.f);
                areg[i].w = fmaxf(fmaf(areg[i].w, a3, b3), 0.f);
            }
        }
        #pragma unroll
        for (int i = 0; i < 2; i++) {
            areg[i].x = f2tf32f(areg[i].x);
            areg[i].y = f2tf32f(areg[i].y);
            areg[i].z = f2tf32f(areg[i].z);
            areg[i].w = f2tf32f(areg[i].w);
        }
    };
    auto sts_A = [&](float* As) {
        *(float4*)(As + a_r0 * ALD + a_c0) = areg[0];
        *(float4*)(As + a_r1 * ALD + a_c0) = areg[1];
    };
    auto cpB = [&](float* Bs, int k0) {
        uint32_t bbase = smem_u32(Bs);
        #pragma unroll
        for (int i = 0; i < 8; i++) {
            int idx = tid + i * 256;
            int r = idx >> 6;
            int c4 = (idx & 63) * 4;
            cp16(bbase + (uint32_t)(r * BLD + c4) * 4,
                 Wt + (size_t)(k0 * 32 + r) * F + c4);
        }
    };

    int buf = 0;
    load_A(0);
    sts_A(sm);
    cpB(sm + ASZ, 0);
    asm volatile("cp.async.commit_group;" ::: "memory");

    for (int k0 = 0; k0 < 8; k0++) {
        if (k0 < 7) load_A(k0 + 1);
        asm volatile("cp.async.wait_group 0;" ::: "memory");
        __syncthreads();
        float* As = sm + buf * STAGE_F;
        float* Bs = As + ASZ;
        if (k0 < 7) {
            float* Asn = sm + (buf ^ 1) * STAGE_F;
            sts_A(Asn);
            cpB(Asn + ASZ, k0 + 1);
            asm volatile("cp.async.commit_group;" ::: "memory");
        }
        #pragma unroll
        for (int kk = 0; kk < 4; kk++) {
            wmma::fragment<wmma::matrix_a, 16, 16, 8, wmma::precision::tf32, wmma::row_major> af[2];
            wmma::fragment<wmma::matrix_b, 16, 16, 8, wmma::precision::tf32, wmma::row_major> bf[4];
            #pragma unroll
            for (int i = 0; i < 2; i++)
                wmma::load_matrix_sync(af[i], As + (warp_row * 32 + i * 16) * ALD + kk * 8, ALD);
            #pragma unroll
            for (int j = 0; j < 4; j++)
                wmma::load_matrix_sync(bf[j], Bs + (kk * 8) * BLD + warp_col * 64 + j * 16, BLD);
            #pragma unroll
            for (int i = 0; i < 2; i++)
                #pragma unroll
                for (int j = 0; j < 4; j++)
                    wmma::mma_sync(acc[i][j], af[i], bf[j], acc[i][j]);
        }
        __syncthreads();
        buf ^= 1;
    }

    // epilogue: frags -> smem -> coalesced fp32 C + fp16 Ch
    float* ep = sm;   // 64 x EPLD
    #pragma unroll
    for (int i = 0; i < 2; i++)
        #pragma unroll
        for (int j = 0; j < 4; j++)
            wmma::store_matrix_sync(ep + (size_t)(warp_row * 32 + i * 16) * EPLD + warp_col * 64 + j * 16,
                                    acc[i][j], EPLD, wmma::mem_row_major);
    __syncthreads();

    #pragma unroll
    for (int it = 0; it < 8; it++) {
        int idx = tid + it * 256;          // 2048 groups of 8 floats
        int r = idx >> 5;
        int g = idx & 31;
        int grow = row0 + r;
        if (grow < M) {
            float4 v0 = *(float4*)(ep + r * EPLD + g * 8);
            float4 v1 = *(float4*)(ep + r * EPLD + g * 8 + 4);
            *(float4*)(C + (size_t)grow * F + g * 8) = v0;
            *(float4*)(C + (size_t)grow * F + g * 8 + 4) = v1;
            __half2 h[4];
            h[0] = __floats2half2_rn(v0.x, v0.y);
            h[1] = __floats2half2_rn(v0.z, v0.w);
            h[2] = __floats2half2_rn(v1.x, v1.y);
            h[3] = __floats2half2_rn(v1.z, v1.w);
            *(uint4*)(Ch + (size_t)grow * F + g * 8) = *reinterpret_cast<uint4*>(h);
        }
    }
}

// ---------------- SpMM: fp16 gather, fp32 self-loop + accumulate ----------------
__global__ void __launch_bounds__(256)
k_spmm(const float* __restrict__ X, const __half* __restrict__ Xh,
       float* __restrict__ Y, int Nn) {
    int gw = (blockIdx.x * 256 + threadIdx.x) >> 5;
    int row = gw >> 1;
    int half = gw & 1;
    int lane = threadIdx.x & 31;
    if (row >= Nn) return;

    float4 acc = *(const float4*)(X + (size_t)row * F + half * 128 + lane * 4);  // self loop fp32

    const __half* Xhh = Xh + half * 128;
    int e = g_ptr[row];
    int end = g_ptr[row + 1];
    while (e < end) {
        int m = end - e;
        int c = 0;
        float vv = 0.f;
        if (lane < m) { c = g_cols[e + lane]; vv = g_vals[e + lane]; }
        int cnt = m < 32 ? m : 32;
        #pragma unroll 4
        for (int j = 0; j < cnt; j++) {
            int cj = __shfl_sync(0xffffffffu, c, j);
            float vj = __shfl_sync(0xffffffffu, vv, j);
            uint2 u = *(const uint2*)(Xhh + (size_t)cj * F + lane * 4);
            float2 f0 = __half22float2(*reinterpret_cast<const __half2*>(&u.x));
            float2 f1 = __half22float2(*reinterpret_cast<const __half2*>(&u.y));
            acc.x = fmaf(vj, f0.x, acc.x);
            acc.y = fmaf(vj, f0.y, acc.y);
            acc.z = fmaf(vj, f1.x, acc.z);
            acc.w = fmaf(vj, f1.y, acc.w);
        }
        e += 32;
    }
    __stcs((float4*)(Y + (size_t)row * F + half * 128 + lane * 4), acc);
}

// ---------------- BN stats ----------------
__global__ void k_stats(const float* __restrict__ H, int M) {
    int c = threadIdx.x;
    float s = 0.f, s2 = 0.f;
    for (int r = blockIdx.x; r < M; r += gridDim.x) {
        float x = __ldcs(H + (size_t)r * F + c);
        s += x;
        s2 = fmaf(x, x, s2);
    }
    atomicAdd(&g_sum[c], s);
    atomicAdd(&g_sumsq[c], s2);
}
__global__ void k_finalize(int M, const float* __restrict__ gamma,
                           const float* __restrict__ beta) {
    int c = threadIdx.x;
    float invM = 1.f / (float)M;
    float m = g_sum[c] * invM;
    float var = g_sumsq[c] * invM - m * m;
    float r = rsqrtf(var + 1e-5f);
    float a = gamma[c] * r;
    g_a[c] = a;
    g_b[c] = beta[c] - m * a;
}

// ---------------- launch ----------------
extern "C" void kernel_launch(void* const* d_in, const int* in_sizes, int n_in,
                              void* d_out, int out_size) {
    const float* feature = (const float*)d_in[0];
    const int*   rows    = (const int*)d_in[1];
    const int*   cols    = (const int*)d_in[2];
    const float* vals    = (const float*)d_in[3];
    const float* W1      = (const float*)d_in[4];
    const float* W2      = (const float*)d_in[5];
    const float* gamma   = (const float*)d_in[6];
    const float* beta    = (const float*)d_in[7];
    float* out = (float*)d_out;

    int N_ = in_sizes[0] / F;
    int E_ = in_sizes[1];

    float *p_support, *p_H, *p_Y;
    __half* p_Xh;
    uint32_t* p_Wt;
    cudaGetSymbolAddress((void**)&p_support, g_support);
    cudaGetSymbolAddress((void**)&p_H, g_H);
    cudaGetSymbolAddress((void**)&p_Y, g_Y);
    cudaGetSymbolAddress((void**)&p_Xh, g_Xh);
    cudaGetSymbolAddress((void**)&p_Wt, g_Wt);

    const int smem_bytes = 2 * STAGE_F * sizeof(float);
    cudaFuncSetAttribute(k_gemm_wmma, cudaFuncAttributeMaxDynamicSharedMemorySize, smem_bytes);

    static cudaStream_t s2 = nullptr;
    static cudaEvent_t evF = nullptr, evJ = nullptr;
    if (!s2) {
        cudaStreamCreateWithFlags(&s2, cudaStreamNonBlocking);
        cudaEventCreateWithFlags(&evF, cudaEventDisableTiming);
        cudaEventCreateWithFlags(&evJ, cudaEventDisableTiming);
    }

    int n_ptr = N_ + 1;
    int nb = (n_ptr + 1023) / 1024;
    int gtiles = (N_ + 63) / 64;
    int spmm_blocks = (2 * N_ * 32 + 255) / 256;

    // fork: CSR build concurrent with weight prep + GEMM1
    cudaEventRecord(evF, 0);
    cudaStreamWaitEvent(s2, evF, 0);

    k_zero<<<(n_ptr + 255) / 256, 256, 0, s2>>>(n_ptr);
    k_hist<<<(E_ + 255) / 256, 256, 0, s2>>>(rows, E_);
    k_scan_block<<<nb, 1024, 0, s2>>>(n_ptr);
    k_scan_sums<<<1, 128, 0, s2>>>(nb);
    k_scan_add<<<nb, 1024, 0, s2>>>(n_ptr);
    k_scatter<<<(E_ + 255) / 256, 256, 0, s2>>>(rows, cols, vals, E_);
    cudaEventRecord(evJ, s2);

    k_prep_w<<<F * F / 256, 256>>>(W1, W2);
    k_gemm_wmma<<<gtiles, 256, smem_bytes>>>(feature, p_Wt, p_support, p_Xh, N_, 0);

    cudaStreamWaitEvent(0, evJ, 0);

    k_spmm<<<spmm_blocks, 256>>>(p_support, p_Xh, p_H, N_);
    k_stats<<<1024, 256>>>(p_H, N_);
    k_finalize<<<1, 256>>>(N_, gamma, beta);
    k_gemm_wmma<<<gtiles, 256, smem_bytes>>>(p_H, p_Wt + F * F, p_Y, p_Xh, N_, 1);
    k_spmm<<<spmm_blocks, 256>>>(p_Y, p_Xh, out, N_);
}